// round 2
// baseline (speedup 1.0000x reference)
#include <cuda_runtime.h>

#define NB 8
#define NL 1000
#define ND 512
#define NH 8
#define NDK 64
#define NR 1999   // 2*max_len - 1

// ---------------- device scratch (allocation-free rule: __device__ globals) ----
__device__ float g_xn[NB * NL * ND];
__device__ float g_q[NB * NH * NL * NDK];
__device__ float g_k[NB * NH * NL * NDK];
__device__ float g_v[NB * NH * NL * NDK];
__device__ float g_ctx[NB * NL * ND];

__device__ __forceinline__ float dot4(float4 a, float4 b) {
    return a.x * b.x + a.y * b.y + a.z * b.z + a.w * b.w;
}

// ---------------- LayerNorm: one block per row of 512 ------------------------
__global__ void ln_kernel(const float* __restrict__ x,
                          const float* __restrict__ gamma,
                          const float* __restrict__ beta) {
    int row = blockIdx.x;
    int tid = threadIdx.x;  // 128 threads, 4 floats each
    const float4 v = ((const float4*)(x + (size_t)row * ND))[tid];
    __shared__ float red[4];

    float s = v.x + v.y + v.z + v.w;
#pragma unroll
    for (int o = 16; o; o >>= 1) s += __shfl_xor_sync(0xffffffffu, s, o);
    if ((tid & 31) == 0) red[tid >> 5] = s;
    __syncthreads();
    float mean = (red[0] + red[1] + red[2] + red[3]) * (1.0f / ND);
    __syncthreads();

    float a = v.x - mean, b = v.y - mean, c = v.z - mean, d = v.w - mean;
    float s2 = a * a + b * b + c * c + d * d;
#pragma unroll
    for (int o = 16; o; o >>= 1) s2 += __shfl_xor_sync(0xffffffffu, s2, o);
    if ((tid & 31) == 0) red[tid >> 5] = s2;
    __syncthreads();
    float var = (red[0] + red[1] + red[2] + red[3]) * (1.0f / ND);
    float inv = rsqrtf(var + 1e-5f);

    const float4 g = ((const float4*)gamma)[tid];
    const float4 bt = ((const float4*)beta)[tid];
    float4 o4;
    o4.x = a * inv * g.x + bt.x;
    o4.y = b * inv * g.y + bt.y;
    o4.z = c * inv * g.z + bt.z;
    o4.w = d * inv * g.w + bt.w;
    ((float4*)(g_xn + (size_t)row * ND))[tid] = o4;
}

// ---------------- 64x64x16 tiled SGEMM (NT): C = A @ W^T + bias --------------
// A: 8000 x 512 row-major; W: 512 x 512 row-major (N x K).
// mode 0: write to (B,H,L,dk) layout (QKV). mode 1: row-major + residual.
__global__ void __launch_bounds__(256) gemm_kernel(
    const float* __restrict__ A, const float* __restrict__ W,
    const float* __restrict__ bias, const float* __restrict__ resid,
    float* __restrict__ C, int mode) {
    __shared__ float As[16][68];
    __shared__ float Bs[16][68];
    const int n0 = blockIdx.x * 64, m0 = blockIdx.y * 64;
    const int tid = threadIdx.x;
    const int ty = tid >> 4, tx = tid & 15;
    const int lm = tid >> 2, lk = (tid & 3) << 2;
    float acc[4][4] = {};

    for (int k0 = 0; k0 < ND; k0 += 16) {
        float4 av = *(const float4*)&A[(size_t)(m0 + lm) * ND + k0 + lk];
        float4 wv = *(const float4*)&W[(size_t)(n0 + lm) * ND + k0 + lk];
        As[lk + 0][lm] = av.x; As[lk + 1][lm] = av.y;
        As[lk + 2][lm] = av.z; As[lk + 3][lm] = av.w;
        Bs[lk + 0][lm] = wv.x; Bs[lk + 1][lm] = wv.y;
        Bs[lk + 2][lm] = wv.z; Bs[lk + 3][lm] = wv.w;
        __syncthreads();
#pragma unroll
        for (int kk = 0; kk < 16; kk++) {
            float4 a4 = *(float4*)&As[kk][ty << 2];
            float4 b4 = *(float4*)&Bs[kk][tx << 2];
            acc[0][0] += a4.x * b4.x; acc[0][1] += a4.x * b4.y;
            acc[0][2] += a4.x * b4.z; acc[0][3] += a4.x * b4.w;
            acc[1][0] += a4.y * b4.x; acc[1][1] += a4.y * b4.y;
            acc[1][2] += a4.y * b4.z; acc[1][3] += a4.y * b4.w;
            acc[2][0] += a4.z * b4.x; acc[2][1] += a4.z * b4.y;
            acc[2][2] += a4.z * b4.z; acc[2][3] += a4.z * b4.w;
            acc[3][0] += a4.w * b4.x; acc[3][1] += a4.w * b4.y;
            acc[3][2] += a4.w * b4.z; acc[3][3] += a4.w * b4.w;
        }
        __syncthreads();
    }

    const int n = n0 + (tx << 2);
    const float4 bb = *(const float4*)&bias[n];
    if (mode == 0) {
        const int h = n >> 6, d = n & 63;
#pragma unroll
        for (int r = 0; r < 4; r++) {
            int m = m0 + (ty << 2) + r;
            int bi = m / NL, l = m - bi * NL;
            float4 o;
            o.x = acc[r][0] + bb.x; o.y = acc[r][1] + bb.y;
            o.z = acc[r][2] + bb.z; o.w = acc[r][3] + bb.w;
            *(float4*)&C[(((size_t)(bi * NH + h) * NL + l) << 6) + d] = o;
        }
    } else {
#pragma unroll
        for (int r = 0; r < 4; r++) {
            size_t off = (size_t)(m0 + (ty << 2) + r) * ND + n;
            float4 rr = *(const float4*)&resid[off];
            float4 o;
            o.x = acc[r][0] + bb.x + rr.x; o.y = acc[r][1] + bb.y + rr.y;
            o.z = acc[r][2] + bb.z + rr.z; o.w = acc[r][3] + bb.w + rr.w;
            *(float4*)&C[off] = o;
        }
    }
}

// ---------------- fused flash attention with relative-position bias ----------
// grid: (16 i-tiles, 64 bh), 256 threads, dynamic smem.
#define SQ 68                      // padded row stride (floats)
#define OFF_Q 0
#define OFF_K (64 * SQ)
#define OFF_V (128 * SQ)
#define OFF_S (192 * SQ)
#define OFF_R (256 * SQ)           // 127 rows
#define OFF_M (OFF_R + 127 * SQ)
#define OFF_L (OFF_M + 64)
#define OFF_A (OFF_L + 64)
#define OFF_P (OFF_A + 64)
#define ATTN_SMEM_FLOATS (OFF_P + 256)
#define ATTN_SMEM_BYTES (ATTN_SMEM_FLOATS * 4)

__global__ void __launch_bounds__(256) attn_kernel(const float* __restrict__ rel) {
    extern __shared__ float sm[];
    float* Qs = sm + OFF_Q;
    float* Ks = sm + OFF_K;
    float* Vs = sm + OFF_V;
    float* Ss = sm + OFF_S;
    float* Rs = sm + OFF_R;
    float* row_m = sm + OFF_M;
    float* row_l = sm + OFF_L;
    float* row_a = sm + OFF_A;
    float* pred = sm + OFF_P;

    const int it = blockIdx.x, bh = blockIdx.y;
    const int b = bh >> 3, h = bh & 7;
    const int i0 = it * 64;
    const int tid = threadIdx.x;
    const int ty = tid >> 4, tx = tid & 15;

    const float* qb = g_q + (size_t)bh * NL * NDK;
    const float* kb = g_k + (size_t)bh * NL * NDK;
    const float* vb = g_v + (size_t)bh * NL * NDK;

    // load Q tile (zero OOB rows)
    for (int idx = tid; idx < 64 * 16; idx += 256) {
        int r = idx >> 4, c4 = (idx & 15) << 2;
        float4 v4 = make_float4(0.f, 0.f, 0.f, 0.f);
        if (i0 + r < NL) v4 = *(const float4*)&qb[(size_t)(i0 + r) * NDK + c4];
        *(float4*)&Qs[r * SQ + c4] = v4;
    }
    if (tid < 64) { row_m[tid] = -1e30f; row_l[tid] = 0.f; }
    float O[4][4] = {};

    for (int jt = 0; jt < 16; jt++) {
        const int j0 = jt * 64;
        // load K (pre-scaled by 1/sqrt(dk)) and V
        for (int idx = tid; idx < 64 * 16; idx += 256) {
            int r = idx >> 4, c4 = (idx & 15) << 2;
            float4 kv = make_float4(0.f, 0.f, 0.f, 0.f);
            float4 vv = make_float4(0.f, 0.f, 0.f, 0.f);
            if (j0 + r < NL) {
                kv = *(const float4*)&kb[(size_t)(j0 + r) * NDK + c4];
                vv = *(const float4*)&vb[(size_t)(j0 + r) * NDK + c4];
            }
            kv.x *= 0.125f; kv.y *= 0.125f; kv.z *= 0.125f; kv.w *= 0.125f;
            *(float4*)&Ks[r * SQ + c4] = kv;
            *(float4*)&Vs[r * SQ + c4] = vv;
        }
        // load rel band: global row = rbase + rr, rr in [0,127)
        const int rbase = j0 - i0 + (NL - 1) - 63;
        for (int idx = tid; idx < 127 * 16; idx += 256) {
            int rr = idx >> 4, c4 = (idx & 15) << 2;
            int rg = rbase + rr;
            float4 v4 = make_float4(0.f, 0.f, 0.f, 0.f);
            if (rg >= 0 && rg < NR) v4 = *(const float4*)&rel[(size_t)rg * NDK + c4];
            *(float4*)&Rs[rr * SQ + c4] = v4;
        }
        __syncthreads();

        // S = (q . k_scaled) + (q . rel[j-i+L-1]) for a 4x4 micro-tile
        float acc[4][4] = {};
        const int ubase = (tx << 2) - (ty << 2) + 60;  // u for c - r = -3
        for (int d4 = 0; d4 < 16; d4++) {
            float4 qv[4], kv[4], rv[7];
#pragma unroll
            for (int r = 0; r < 4; r++) qv[r] = *(float4*)&Qs[((ty << 2) + r) * SQ + (d4 << 2)];
#pragma unroll
            for (int c = 0; c < 4; c++) kv[c] = *(float4*)&Ks[((tx << 2) + c) * SQ + (d4 << 2)];
#pragma unroll
            for (int u = 0; u < 7; u++) rv[u] = *(float4*)&Rs[(ubase + u) * SQ + (d4 << 2)];
#pragma unroll
            for (int r = 0; r < 4; r++)
#pragma unroll
                for (int c = 0; c < 4; c++)
                    acc[r][c] += dot4(qv[r], kv[c]) + dot4(qv[r], rv[c - r + 3]);
        }
#pragma unroll
        for (int r = 0; r < 4; r++)
#pragma unroll
            for (int c = 0; c < 4; c++) {
                float sval = acc[r][c];
                if (j0 + (tx << 2) + c >= NL) sval = -1e30f;
                Ss[((ty << 2) + r) * SQ + (tx << 2) + c] = sval;
            }
        __syncthreads();

        // online softmax: 4 threads per row
        {
            int rr = tid >> 2, part = (tid & 3) * 16;
            float mx = -1e30f;
#pragma unroll
            for (int cc = 0; cc < 16; cc++) mx = fmaxf(mx, Ss[rr * SQ + part + cc]);
            pred[tid] = mx;
        }
        __syncthreads();
        if (tid < 64) {
            float mold = row_m[tid];
            float mnew = fmaxf(fmaxf(pred[tid * 4], pred[tid * 4 + 1]),
                               fmaxf(pred[tid * 4 + 2], pred[tid * 4 + 3]));
            mnew = fmaxf(mold, mnew);
            row_a[tid] = __expf(mold - mnew);
            row_m[tid] = mnew;
        }
        __syncthreads();
        {
#pragma unroll
            for (int r = 0; r < 4; r++) {
                float al = row_a[(ty << 2) + r];
                O[r][0] *= al; O[r][1] *= al; O[r][2] *= al; O[r][3] *= al;
            }
            int rr = tid >> 2, part = (tid & 3) * 16;
            float m = row_m[rr];
            float ssum = 0.f;
#pragma unroll
            for (int cc = 0; cc < 16; cc++) {
                float e = __expf(Ss[rr * SQ + part + cc] - m);
                Ss[rr * SQ + part + cc] = e;
                ssum += e;
            }
            pred[tid] = ssum;
        }
        __syncthreads();
        if (tid < 64)
            row_l[tid] = row_l[tid] * row_a[tid] +
                         pred[tid * 4] + pred[tid * 4 + 1] + pred[tid * 4 + 2] + pred[tid * 4 + 3];

        // O += P @ V
        for (int l4 = 0; l4 < 16; l4++) {
            float4 p0 = *(float4*)&Ss[((ty << 2) + 0) * SQ + (l4 << 2)];
            float4 p1 = *(float4*)&Ss[((ty << 2) + 1) * SQ + (l4 << 2)];
            float4 p2 = *(float4*)&Ss[((ty << 2) + 2) * SQ + (l4 << 2)];
            float4 p3 = *(float4*)&Ss[((ty << 2) + 3) * SQ + (l4 << 2)];
            float4 v0 = *(float4*)&Vs[((l4 << 2) + 0) * SQ + (tx << 2)];
            float4 v1 = *(float4*)&Vs[((l4 << 2) + 1) * SQ + (tx << 2)];
            float4 v2 = *(float4*)&Vs[((l4 << 2) + 2) * SQ + (tx << 2)];
            float4 v3 = *(float4*)&Vs[((l4 << 2) + 3) * SQ + (tx << 2)];
#define PVROW(r, p)                                                          \
            O[r][0] += p.x * v0.x + p.y * v1.x + p.z * v2.x + p.w * v3.x;    \
            O[r][1] += p.x * v0.y + p.y * v1.y + p.z * v2.y + p.w * v3.y;    \
            O[r][2] += p.x * v0.z + p.y * v1.z + p.z * v2.z + p.w * v3.z;    \
            O[r][3] += p.x * v0.w + p.y * v1.w + p.z * v2.w + p.w * v3.w;
            PVROW(0, p0) PVROW(1, p1) PVROW(2, p2) PVROW(3, p3)
#undef PVROW
        }
        __syncthreads();
    }

    // normalize + write ctx in (B, L, D) layout
#pragma unroll
    for (int r = 0; r < 4; r++) {
        int gi = i0 + (ty << 2) + r;
        if (gi < NL) {
            float invl = 1.0f / row_l[(ty << 2) + r];
            float4 o;
            o.x = O[r][0] * invl; o.y = O[r][1] * invl;
            o.z = O[r][2] * invl; o.w = O[r][3] * invl;
            *(float4*)&g_ctx[((size_t)(b * NL + gi)) * ND + (h << 6) + (tx << 2)] = o;
        }
    }
}

// ---------------- launch ------------------------------------------------------
extern "C" void kernel_launch(void* const* d_in, const int* in_sizes, int n_in,
                              void* d_out, int out_size) {
    const float* x     = (const float*)d_in[0];
    const float* Wq    = (const float*)d_in[1];
    const float* bq    = (const float*)d_in[2];
    const float* Wk    = (const float*)d_in[3];
    const float* bk    = (const float*)d_in[4];
    const float* Wv    = (const float*)d_in[5];
    const float* bv    = (const float*)d_in[6];
    const float* Wo    = (const float*)d_in[7];
    const float* bo    = (const float*)d_in[8];
    const float* rel   = (const float*)d_in[9];
    const float* gamma = (const float*)d_in[10];
    const float* beta  = (const float*)d_in[11];
    float* out = (float*)d_out;

    void *pxn = nullptr, *pq = nullptr, *pk = nullptr, *pv = nullptr, *pctx = nullptr;
    cudaGetSymbolAddress(&pxn, g_xn);
    cudaGetSymbolAddress(&pq, g_q);
    cudaGetSymbolAddress(&pk, g_k);
    cudaGetSymbolAddress(&pv, g_v);
    cudaGetSymbolAddress(&pctx, g_ctx);

    cudaFuncSetAttribute(attn_kernel, cudaFuncAttributeMaxDynamicSharedMemorySize,
                         ATTN_SMEM_BYTES);

    ln_kernel<<<NB * NL, 128>>>(x, gamma, beta);

    dim3 gg(ND / 64, (NB * NL) / 64);  // (8, 125)
    gemm_kernel<<<gg, 256>>>((const float*)pxn, Wq, bq, nullptr, (float*)pq, 0);
    gemm_kernel<<<gg, 256>>>((const float*)pxn, Wk, bk, nullptr, (float*)pk, 0);
    gemm_kernel<<<gg, 256>>>((const float*)pxn, Wv, bv, nullptr, (float*)pv, 0);

    attn_kernel<<<dim3(16, NB * NH), 256, ATTN_SMEM_BYTES>>>(rel);

    gemm_kernel<<<gg, 256>>>((const float*)pctx, Wo, bo, x, out, 1);
}

// round 4
// speedup vs baseline: 1.9103x; 1.9103x over previous
#include <cuda_runtime.h>

#define NB 8
#define NL 1000
#define ND 512
#define NH 8
#define NDK 64
#define NR 1999   // 2*max_len - 1

// ---------------- device scratch (allocation-free rule) -----------------------
__device__ float g_xn[NB * NL * ND];
__device__ float g_q[NB * NH * NL * NDK];
__device__ float g_k[NB * NH * NL * NDK];
__device__ float g_v[NB * NH * NL * NDK];
__device__ float g_ctx[NB * NL * ND];

// ---------------- tf32 helpers ------------------------------------------------
__device__ __forceinline__ float f2tf(float f) {
    unsigned u;
    asm("cvt.rna.tf32.f32 %0, %1;" : "=r"(u) : "f"(f));
    return __uint_as_float(u);
}

// D(16x8,f32) += A(16x8,tf32,row) * B(8x8,tf32,col)
__device__ __forceinline__ void mma8(float4& d, float4 a, float2 b) {
    asm volatile(
        "mma.sync.aligned.m16n8k8.row.col.f32.tf32.tf32.f32 "
        "{%0,%1,%2,%3}, {%4,%5,%6,%7}, {%8,%9}, {%0,%1,%2,%3};\n"
        : "+f"(d.x), "+f"(d.y), "+f"(d.z), "+f"(d.w)
        : "r"(__float_as_uint(a.x)), "r"(__float_as_uint(a.y)),
          "r"(__float_as_uint(a.z)), "r"(__float_as_uint(a.w)),
          "r"(__float_as_uint(b.x)), "r"(__float_as_uint(b.y)));
}

// Fragment-permuted smem layouts.
// A-operand: 16x8 tiles, element (m,k): lane=(m&7)*4+(k&3), reg=((m>>3)&1)+((k>>2)&1)*2
__device__ __forceinline__ int a_off(int m, int k, int nkt) {
    return (((m >> 4) * nkt + (k >> 3)) << 7) +
           ((((m & 7) << 2) + (k & 3)) << 2) + ((m >> 3) & 1) + (((k >> 2) & 1) << 1);
}
// B-operand: 8x8 tiles, element (k,n): lane=(n&7)*4+(k&3), reg=(k>>2)&1
__device__ __forceinline__ int b_off(int k, int n, int nnt) {
    return (((k >> 3) * nnt + (n >> 3)) << 6) +
           ((((n & 7) << 2) + (k & 3)) << 1) + ((k >> 2) & 1);
}

// ---------------- LayerNorm ---------------------------------------------------
__global__ void ln_kernel(const float* __restrict__ x,
                          const float* __restrict__ gamma,
                          const float* __restrict__ beta) {
    int row = blockIdx.x;
    int tid = threadIdx.x;
    const float4 v = ((const float4*)(x + (size_t)row * ND))[tid];
    __shared__ float red[4];

    float s = v.x + v.y + v.z + v.w;
#pragma unroll
    for (int o = 16; o; o >>= 1) s += __shfl_xor_sync(0xffffffffu, s, o);
    if ((tid & 31) == 0) red[tid >> 5] = s;
    __syncthreads();
    float mean = (red[0] + red[1] + red[2] + red[3]) * (1.0f / ND);
    __syncthreads();

    float a = v.x - mean, b = v.y - mean, c = v.z - mean, d = v.w - mean;
    float s2 = a * a + b * b + c * c + d * d;
#pragma unroll
    for (int o = 16; o; o >>= 1) s2 += __shfl_xor_sync(0xffffffffu, s2, o);
    if ((tid & 31) == 0) red[tid >> 5] = s2;
    __syncthreads();
    float var = (red[0] + red[1] + red[2] + red[3]) * (1.0f / ND);
    float inv = rsqrtf(var + 1e-5f);

    const float4 gg = ((const float4*)gamma)[tid];
    const float4 bt = ((const float4*)beta)[tid];
    float4 o4;
    o4.x = a * inv * gg.x + bt.x;
    o4.y = b * inv * gg.y + bt.y;
    o4.z = c * inv * gg.z + bt.z;
    o4.w = d * inv * gg.w + bt.w;
    ((float4*)(g_xn + (size_t)row * ND))[tid] = o4;
}

// ---------------- tf32 tensor-core GEMM: C = A @ W^T + bias ------------------
// Block tile 64(M) x 128(N), k-step 32. 8 warps, warp tile 32x32.
__global__ void __launch_bounds__(256) gemm_kernel(
    const float* __restrict__ A, const float* __restrict__ W,
    const float* __restrict__ bias, const float* __restrict__ resid,
    float* __restrict__ C, int mode) {
    __shared__ float As[2048];  // 4 mt x 4 kt tiles
    __shared__ float Bs[4096];  // 4 kt x 16 nt tiles
    const int tid = threadIdx.x;
    const int lane = tid & 31, warp = tid >> 5;
    const int wm = warp >> 2, wn = warp & 3;
    const int g = lane >> 2, tig = lane & 3;
    const int m0 = blockIdx.y * 64, n0 = blockIdx.x * 128;
    float4 acc[2][4] = {};

    for (int k0 = 0; k0 < ND; k0 += 32) {
#pragma unroll
        for (int i = 0; i < 2; i++) {
            int f = tid + (i << 8);
            int m = f >> 3, kq = (f & 7) << 2;
            float4 v = *(const float4*)&A[(size_t)(m0 + m) * ND + k0 + kq];
            As[a_off(m, kq + 0, 4)] = f2tf(v.x);
            As[a_off(m, kq + 1, 4)] = f2tf(v.y);
            As[a_off(m, kq + 2, 4)] = f2tf(v.z);
            As[a_off(m, kq + 3, 4)] = f2tf(v.w);
        }
#pragma unroll
        for (int i = 0; i < 4; i++) {
            int f = tid + (i << 8);
            int n = f >> 3, kq = (f & 7) << 2;
            float4 v = *(const float4*)&W[(size_t)(n0 + n) * ND + k0 + kq];
            Bs[b_off(kq + 0, n, 16)] = f2tf(v.x);
            Bs[b_off(kq + 1, n, 16)] = f2tf(v.y);
            Bs[b_off(kq + 2, n, 16)] = f2tf(v.z);
            Bs[b_off(kq + 3, n, 16)] = f2tf(v.w);
        }
        __syncthreads();
#pragma unroll
        for (int kt = 0; kt < 4; kt++) {
            float4 a0 = *(float4*)&As[((((wm << 1) + 0) * 4 + kt) << 7) + (lane << 2)];
            float4 a1 = *(float4*)&As[((((wm << 1) + 1) * 4 + kt) << 7) + (lane << 2)];
            float2 bf[4];
#pragma unroll
            for (int j = 0; j < 4; j++)
                bf[j] = *(float2*)&Bs[((kt * 16 + (wn << 2) + j) << 6) + (lane << 1)];
#pragma unroll
            for (int j = 0; j < 4; j++) {
                mma8(acc[0][j], a0, bf[j]);
                mma8(acc[1][j], a1, bf[j]);
            }
        }
        __syncthreads();
    }

#pragma unroll
    for (int i = 0; i < 2; i++) {
#pragma unroll
        for (int j = 0; j < 4; j++) {
            int col = n0 + wn * 32 + j * 8 + (tig << 1);
            float2 bb = *(const float2*)&bias[col];
            float4 c = acc[i][j];
            int r0 = m0 + wm * 32 + i * 16 + g, r1 = r0 + 8;
            if (mode == 0) {
                int h = col >> 6, d = col & 63;
                int b0i = r0 / NL, l0 = r0 - b0i * NL;
                int b1i = r1 / NL, l1 = r1 - b1i * NL;
                *(float2*)&C[(((size_t)(b0i * NH + h) * NL + l0) << 6) + d] =
                    make_float2(c.x + bb.x, c.y + bb.y);
                *(float2*)&C[(((size_t)(b1i * NH + h) * NL + l1) << 6) + d] =
                    make_float2(c.z + bb.x, c.w + bb.y);
            } else {
                size_t o0 = (size_t)r0 * ND + col, o1 = (size_t)r1 * ND + col;
                float2 rr0 = *(const float2*)&resid[o0];
                float2 rr1 = *(const float2*)&resid[o1];
                *(float2*)&C[o0] = make_float2(c.x + bb.x + rr0.x, c.y + bb.y + rr0.y);
                *(float2*)&C[o1] = make_float2(c.z + bb.x + rr1.x, c.w + bb.y + rr1.y);
            }
        }
    }
}

// ---------------- tensor-core flash attention with rel-pos bias --------------
// Per block: one (bh, 64-row i-tile). 8 warps.
// S1 = Q @ K^T (scaled), S2 = Q @ RelBand^T (64x128), gather during softmax,
// O += P @ V. All mma tf32.
#define OFF_Q 0          // A-layout, 4096 floats
#define OFF_K 4096       // B-layout nnt=8
#define OFF_V 8192       // B-layout: k=j (seq), n=d (head dim), nnt=8
#define OFF_P 12288      // A-layout
#define OFF_R 16384      // B-layout nnt=16, 8192 floats
#define OFF_S1 24576     // [64][68] f32
#define OFF_S2 28928     // [64][132] f32
#define OFF_M 37376
#define OFF_L 37440
#define OFF_A 37504
#define ATTN_SMEM_BYTES ((37504 + 64) * 4)

__global__ void __launch_bounds__(256) attn_kernel(const float* __restrict__ rel) {
    extern __shared__ float sm[];
    float* Qs = sm + OFF_Q;
    float* Ks = sm + OFF_K;
    float* Vs = sm + OFF_V;
    float* Ps = sm + OFF_P;
    float* Rs = sm + OFF_R;
    float* S1s = sm + OFF_S1;
    float* S2s = sm + OFF_S2;
    float* row_m = sm + OFF_M;
    float* row_l = sm + OFF_L;
    float* row_a = sm + OFF_A;

    const int it = blockIdx.x, bh = blockIdx.y;
    const int b = bh >> 3, h = bh & 7;
    const int i0 = it << 6;
    const int tid = threadIdx.x;
    const int lane = tid & 31, warp = tid >> 5;
    const int g = lane >> 2, tig = lane & 3;

    const float* qb = g_q + (size_t)bh * NL * NDK;
    const float* kb = g_k + (size_t)bh * NL * NDK;
    const float* vb = g_v + (size_t)bh * NL * NDK;

    // load Q tile into A-layout (zero OOB rows)
#pragma unroll
    for (int i = 0; i < 4; i++) {
        int f = tid + (i << 8);
        int r = f >> 4, c4 = (f & 15) << 2;
        float4 v = make_float4(0.f, 0.f, 0.f, 0.f);
        if (i0 + r < NL) v = *(const float4*)&qb[(size_t)(i0 + r) * NDK + c4];
        Qs[a_off(r, c4 + 0, 8)] = f2tf(v.x);
        Qs[a_off(r, c4 + 1, 8)] = f2tf(v.y);
        Qs[a_off(r, c4 + 2, 8)] = f2tf(v.z);
        Qs[a_off(r, c4 + 3, 8)] = f2tf(v.w);
    }
    if (tid < 64) { row_m[tid] = -1e30f; row_l[tid] = 0.f; }
    float4 O[4] = {};
    __syncthreads();

    for (int jt = 0; jt < 16; jt++) {
        const int j0 = jt << 6;
        // K (pre-scaled, B-layout k=d,n=j) and V (B-layout k=j,n=d)
#pragma unroll
        for (int i = 0; i < 4; i++) {
            int f = tid + (i << 8);
            int r = f >> 4, c4 = (f & 15) << 2;
            float4 kv = make_float4(0.f, 0.f, 0.f, 0.f);
            float4 vv = make_float4(0.f, 0.f, 0.f, 0.f);
            if (j0 + r < NL) {
                kv = *(const float4*)&kb[(size_t)(j0 + r) * NDK + c4];
                vv = *(const float4*)&vb[(size_t)(j0 + r) * NDK + c4];
            }
            Ks[b_off(c4 + 0, r, 8)] = f2tf(kv.x * 0.125f);
            Ks[b_off(c4 + 1, r, 8)] = f2tf(kv.y * 0.125f);
            Ks[b_off(c4 + 2, r, 8)] = f2tf(kv.z * 0.125f);
            Ks[b_off(c4 + 3, r, 8)] = f2tf(kv.w * 0.125f);
            // FIX: V enters PV mma contracted over j (sequence), so k=r, n=c4.
            Vs[b_off(r, c4 + 0, 8)] = f2tf(vv.x);
            Vs[b_off(r, c4 + 1, 8)] = f2tf(vv.y);
            Vs[b_off(r, c4 + 2, 8)] = f2tf(vv.z);
            Vs[b_off(r, c4 + 3, 8)] = f2tf(vv.w);
        }
        // rel band (128 rows) into B-layout
        const int rbase = j0 - i0 + (NL - 1) - 63;
#pragma unroll
        for (int i = 0; i < 8; i++) {
            int f = tid + (i << 8);
            int r = f >> 4, c4 = (f & 15) << 2;
            int rg = rbase + r;
            float4 v = make_float4(0.f, 0.f, 0.f, 0.f);
            if (rg >= 0 && rg < NR) v = *(const float4*)&rel[(size_t)rg * NDK + c4];
            Rs[b_off(c4 + 0, r, 16)] = f2tf(v.x);
            Rs[b_off(c4 + 1, r, 16)] = f2tf(v.y);
            Rs[b_off(c4 + 2, r, 16)] = f2tf(v.z);
            Rs[b_off(c4 + 3, r, 16)] = f2tf(v.w);
        }
        __syncthreads();

        // S1 = Q @ K^T : warp owns n8-tile `warp`
        {
            float4 s[4] = {};
#pragma unroll
            for (int kt = 0; kt < 8; kt++) {
                float2 bfr = *(float2*)&Ks[((kt * 8 + warp) << 6) + (lane << 1)];
#pragma unroll
                for (int mt = 0; mt < 4; mt++) {
                    float4 afr = *(float4*)&Qs[((mt * 8 + kt) << 7) + (lane << 2)];
                    mma8(s[mt], afr, bfr);
                }
            }
            int col = (warp << 3) + (tig << 1);
#pragma unroll
            for (int mt = 0; mt < 4; mt++) {
                int r0 = (mt << 4) + g;
                *(float2*)&S1s[r0 * 68 + col] = make_float2(s[mt].x, s[mt].y);
                *(float2*)&S1s[(r0 + 8) * 68 + col] = make_float2(s[mt].z, s[mt].w);
            }
        }
        // S2 = Q @ RelBand^T : warp owns n8-tiles {2w, 2w+1}
        {
            float4 s[4][2] = {};
#pragma unroll
            for (int kt = 0; kt < 8; kt++) {
                float2 b0 = *(float2*)&Rs[((kt * 16 + (warp << 1) + 0) << 6) + (lane << 1)];
                float2 b1 = *(float2*)&Rs[((kt * 16 + (warp << 1) + 1) << 6) + (lane << 1)];
#pragma unroll
                for (int mt = 0; mt < 4; mt++) {
                    float4 afr = *(float4*)&Qs[((mt * 8 + kt) << 7) + (lane << 2)];
                    mma8(s[mt][0], afr, b0);
                    mma8(s[mt][1], afr, b1);
                }
            }
#pragma unroll
            for (int mt = 0; mt < 4; mt++)
#pragma unroll
                for (int nl = 0; nl < 2; nl++) {
                    int col = (((warp << 1) + nl) << 3) + (tig << 1);
                    int r0 = (mt << 4) + g;
                    *(float2*)&S2s[r0 * 132 + col] = make_float2(s[mt][nl].x, s[mt][nl].y);
                    *(float2*)&S2s[(r0 + 8) * 132 + col] = make_float2(s[mt][nl].z, s[mt][nl].w);
                }
        }
        __syncthreads();

        // online softmax with rel gather: S[i][c] = S1[i][c] + S2[i][c-i+63]
        {
            int i = tid >> 2, q = tid & 3;
            int cbase = q << 4;
            float mx = -1e30f;
#pragma unroll
            for (int c = 0; c < 16; c++) {
                int cc = cbase + c;
                float s = S1s[i * 68 + cc] + S2s[i * 132 + cc - i + 63];
                if (j0 + cc >= NL) s = -1e30f;
                mx = fmaxf(mx, s);
            }
            mx = fmaxf(mx, __shfl_xor_sync(0xffffffffu, mx, 1));
            mx = fmaxf(mx, __shfl_xor_sync(0xffffffffu, mx, 2));
            float mold = row_m[i];
            float mnew = fmaxf(mold, mx);
            float alpha = __expf(mold - mnew);
            float ssum = 0.f;
#pragma unroll
            for (int c = 0; c < 16; c++) {
                int cc = cbase + c;
                float s = S1s[i * 68 + cc] + S2s[i * 132 + cc - i + 63];
                float e = (j0 + cc >= NL) ? 0.f : __expf(s - mnew);
                ssum += e;
                Ps[a_off(i, cc, 8)] = f2tf(e);
            }
            ssum += __shfl_xor_sync(0xffffffffu, ssum, 1);
            ssum += __shfl_xor_sync(0xffffffffu, ssum, 2);
            if (q == 0) {
                row_m[i] = mnew;
                row_a[i] = alpha;
                row_l[i] = row_l[i] * alpha + ssum;
            }
        }
        __syncthreads();

        // rescale O then O += P @ V (warp owns n8-tile `warp` of dk)
        {
#pragma unroll
            for (int mt = 0; mt < 4; mt++) {
                float a0 = row_a[(mt << 4) + g];
                float a1 = row_a[(mt << 4) + 8 + g];
                O[mt].x *= a0; O[mt].y *= a0;
                O[mt].z *= a1; O[mt].w *= a1;
            }
#pragma unroll
            for (int kt = 0; kt < 8; kt++) {
                float2 bfr = *(float2*)&Vs[((kt * 8 + warp) << 6) + (lane << 1)];
#pragma unroll
                for (int mt = 0; mt < 4; mt++) {
                    float4 afr = *(float4*)&Ps[((mt * 8 + kt) << 7) + (lane << 2)];
                    mma8(O[mt], afr, bfr);
                }
            }
        }
        __syncthreads();
    }

    // normalize + write ctx into (B, L, D)
#pragma unroll
    for (int mt = 0; mt < 4; mt++) {
        int r0 = (mt << 4) + g, r1 = r0 + 8;
        int col = (warp << 3) + (tig << 1);
        if (i0 + r0 < NL) {
            float inv = 1.f / row_l[r0];
            *(float2*)&g_ctx[((size_t)(b * NL + i0 + r0)) * ND + (h << 6) + col] =
                make_float2(O[mt].x * inv, O[mt].y * inv);
        }
        if (i0 + r1 < NL) {
            float inv = 1.f / row_l[r1];
            *(float2*)&g_ctx[((size_t)(b * NL + i0 + r1)) * ND + (h << 6) + col] =
                make_float2(O[mt].z * inv, O[mt].w * inv);
        }
    }
}

// ---------------- launch ------------------------------------------------------
extern "C" void kernel_launch(void* const* d_in, const int* in_sizes, int n_in,
                              void* d_out, int out_size) {
    const float* x     = (const float*)d_in[0];
    const float* Wq    = (const float*)d_in[1];
    const float* bq    = (const float*)d_in[2];
    const float* Wk    = (const float*)d_in[3];
    const float* bk    = (const float*)d_in[4];
    const float* Wv    = (const float*)d_in[5];
    const float* bv    = (const float*)d_in[6];
    const float* Wo    = (const float*)d_in[7];
    const float* bo    = (const float*)d_in[8];
    const float* rel   = (const float*)d_in[9];
    const float* gamma = (const float*)d_in[10];
    const float* beta  = (const float*)d_in[11];
    float* out = (float*)d_out;

    void *pxn = nullptr, *pq = nullptr, *pk = nullptr, *pv = nullptr, *pctx = nullptr;
    cudaGetSymbolAddress(&pxn, g_xn);
    cudaGetSymbolAddress(&pq, g_q);
    cudaGetSymbolAddress(&pk, g_k);
    cudaGetSymbolAddress(&pv, g_v);
    cudaGetSymbolAddress(&pctx, g_ctx);

    cudaFuncSetAttribute(attn_kernel, cudaFuncAttributeMaxDynamicSharedMemorySize,
                         ATTN_SMEM_BYTES);

    ln_kernel<<<NB * NL, 128>>>(x, gamma, beta);

    dim3 gg(ND / 128, (NB * NL) / 64);  // (4, 125)
    gemm_kernel<<<gg, 256>>>((const float*)pxn, Wq, bq, nullptr, (float*)pq, 0);
    gemm_kernel<<<gg, 256>>>((const float*)pxn, Wk, bk, nullptr, (float*)pk, 0);
    gemm_kernel<<<gg, 256>>>((const float*)pxn, Wv, bv, nullptr, (float*)pv, 0);

    attn_kernel<<<dim3(16, NB * NH), 256, ATTN_SMEM_BYTES>>>(rel);

    gemm_kernel<<<gg, 256>>>((const float*)pctx, Wo, bo, x, out, 1);
}

// round 5
// speedup vs baseline: 3.4353x; 1.7983x over previous
#include <cuda_runtime.h>
#include <cuda_bf16.h>

#define NB 8
#define NL 1000
#define ND 512
#define NH 8
#define NDK 64
#define NR 1999   // 2*max_len - 1

// ---------------- device scratch (allocation-free rule) -----------------------
__device__ float g_xn[NB * NL * ND];
__device__ float g_q[NB * NH * NL * NDK];
__device__ float g_k[NB * NH * NL * NDK];
__device__ float g_v[NB * NH * NL * NDK];
__device__ float g_ctx[NB * NL * ND];

// ---------------- bf16 helpers ------------------------------------------------
// pack two f32 into one u32: low half = lo, high half = hi
__device__ __forceinline__ unsigned bf2(float lo, float hi) {
    unsigned r;
    asm("cvt.rn.bf16x2.f32 %0, %1, %2;" : "=r"(r) : "f"(hi), "f"(lo));
    return r;
}

// D(16x8,f32) += A(16x16,bf16,row) * B(16x8,bf16,col)
__device__ __forceinline__ void mma16(float4& d, uint4 a, uint2 b) {
    asm volatile(
        "mma.sync.aligned.m16n8k16.row.col.f32.bf16.bf16.f32 "
        "{%0,%1,%2,%3}, {%4,%5,%6,%7}, {%8,%9}, {%0,%1,%2,%3};\n"
        : "+f"(d.x), "+f"(d.y), "+f"(d.z), "+f"(d.w)
        : "r"(a.x), "r"(a.y), "r"(a.z), "r"(a.w), "r"(b.x), "r"(b.y));
}

// Fragment-permuted smem layouts, u32 (bf16x2 over k) units.
// A tile 16x16: elem (m,k): reg=((m>>3)&1)+((k>>3)&1)*2, lane=(m&7)*4+((k&7)>>1), half=k&1
__device__ __forceinline__ int a_off16(int m, int k, int nkt16) {
    return (((m >> 4) * nkt16 + (k >> 4)) << 7) +
           ((((m & 7) << 2) + ((k & 7) >> 1)) << 2) + ((m >> 3) & 1) + (((k >> 3) & 1) << 1);
}
// B tile 16x8: elem (k,n): reg=(k>>3)&1, lane=(n&7)*4+((k&7)>>1), half=k&1
__device__ __forceinline__ int b_off16(int k, int n, int nnt) {
    return (((k >> 4) * nnt + (n >> 3)) << 6) +
           ((((n & 7) << 2) + ((k & 7) >> 1)) << 1) + ((k >> 3) & 1);
}

// ---------------- LayerNorm ---------------------------------------------------
__global__ void ln_kernel(const float* __restrict__ x,
                          const float* __restrict__ gamma,
                          const float* __restrict__ beta) {
    int row = blockIdx.x;
    int tid = threadIdx.x;
    const float4 v = ((const float4*)(x + (size_t)row * ND))[tid];
    __shared__ float red[4];

    float s = v.x + v.y + v.z + v.w;
#pragma unroll
    for (int o = 16; o; o >>= 1) s += __shfl_xor_sync(0xffffffffu, s, o);
    if ((tid & 31) == 0) red[tid >> 5] = s;
    __syncthreads();
    float mean = (red[0] + red[1] + red[2] + red[3]) * (1.0f / ND);
    __syncthreads();

    float a = v.x - mean, b = v.y - mean, c = v.z - mean, d = v.w - mean;
    float s2 = a * a + b * b + c * c + d * d;
#pragma unroll
    for (int o = 16; o; o >>= 1) s2 += __shfl_xor_sync(0xffffffffu, s2, o);
    if ((tid & 31) == 0) red[tid >> 5] = s2;
    __syncthreads();
    float var = (red[0] + red[1] + red[2] + red[3]) * (1.0f / ND);
    float inv = rsqrtf(var + 1e-5f);

    const float4 gg = ((const float4*)gamma)[tid];
    const float4 bt = ((const float4*)beta)[tid];
    float4 o4;
    o4.x = a * inv * gg.x + bt.x;
    o4.y = b * inv * gg.y + bt.y;
    o4.z = c * inv * gg.z + bt.z;
    o4.w = d * inv * gg.w + bt.w;
    ((float4*)(g_xn + (size_t)row * ND))[tid] = o4;
}

// ---------------- bf16 tensor-core GEMM: C = A @ W^T + bias ------------------
// Block tile 64(M) x 128(N), k-step 32. 8 warps, warp tile 32x32.
__global__ void __launch_bounds__(256) gemm_kernel(
    const float* __restrict__ A, const float* __restrict__ W,
    const float* __restrict__ bias, const float* __restrict__ resid,
    float* __restrict__ C, int mode) {
    __shared__ unsigned As[1024];  // 64m x 32k bf16 (4 mt x 2 kt16 tiles)
    __shared__ unsigned Bs[2048];  // 32k x 128n bf16 (2 kt16 x 16 nt tiles)
    const int tid = threadIdx.x;
    const int lane = tid & 31, warp = tid >> 5;
    const int wm = warp >> 2, wn = warp & 3;
    const int g = lane >> 2, tig = lane & 3;
    const int m0 = blockIdx.y * 64, n0 = blockIdx.x * 128;
    float4 acc[2][4] = {};

    for (int k0 = 0; k0 < ND; k0 += 32) {
#pragma unroll
        for (int i = 0; i < 2; i++) {
            int f = tid + (i << 8);
            int m = f >> 3, kq = (f & 7) << 2;
            float4 v = *(const float4*)&A[(size_t)(m0 + m) * ND + k0 + kq];
            As[a_off16(m, kq, 2)] = bf2(v.x, v.y);
            As[a_off16(m, kq + 2, 2)] = bf2(v.z, v.w);
        }
#pragma unroll
        for (int i = 0; i < 4; i++) {
            int f = tid + (i << 8);
            int n = f >> 3, kq = (f & 7) << 2;
            float4 v = *(const float4*)&W[(size_t)(n0 + n) * ND + k0 + kq];
            Bs[b_off16(kq, n, 16)] = bf2(v.x, v.y);
            Bs[b_off16(kq + 2, n, 16)] = bf2(v.z, v.w);
        }
        __syncthreads();
#pragma unroll
        for (int kt = 0; kt < 2; kt++) {
            uint4 a0 = *(uint4*)&As[((((wm << 1) + 0) * 2 + kt) << 7) + (lane << 2)];
            uint4 a1 = *(uint4*)&As[((((wm << 1) + 1) * 2 + kt) << 7) + (lane << 2)];
            uint2 bf[4];
#pragma unroll
            for (int j = 0; j < 4; j++)
                bf[j] = *(uint2*)&Bs[((kt * 16 + (wn << 2) + j) << 6) + (lane << 1)];
#pragma unroll
            for (int j = 0; j < 4; j++) {
                mma16(acc[0][j], a0, bf[j]);
                mma16(acc[1][j], a1, bf[j]);
            }
        }
        __syncthreads();
    }

#pragma unroll
    for (int i = 0; i < 2; i++) {
#pragma unroll
        for (int j = 0; j < 4; j++) {
            int col = n0 + wn * 32 + j * 8 + (tig << 1);
            float2 bb = *(const float2*)&bias[col];
            float4 c = acc[i][j];
            int r0 = m0 + wm * 32 + i * 16 + g, r1 = r0 + 8;
            if (mode == 0) {
                int h = col >> 6, d = col & 63;
                int b0i = r0 / NL, l0 = r0 - b0i * NL;
                int b1i = r1 / NL, l1 = r1 - b1i * NL;
                *(float2*)&C[(((size_t)(b0i * NH + h) * NL + l0) << 6) + d] =
                    make_float2(c.x + bb.x, c.y + bb.y);
                *(float2*)&C[(((size_t)(b1i * NH + h) * NL + l1) << 6) + d] =
                    make_float2(c.z + bb.x, c.w + bb.y);
            } else {
                size_t o0 = (size_t)r0 * ND + col, o1 = (size_t)r1 * ND + col;
                float2 rr0 = *(const float2*)&resid[o0];
                float2 rr1 = *(const float2*)&resid[o1];
                *(float2*)&C[o0] = make_float2(c.x + bb.x + rr0.x, c.y + bb.y + rr0.y);
                *(float2*)&C[o1] = make_float2(c.z + bb.x + rr1.x, c.w + bb.y + rr1.y);
            }
        }
    }
}

// ---------------- bf16 tensor-core flash attention with rel-pos bias ---------
// Word offsets into dynamic smem (u32/f32 both 4B):
#define OFF_Q 0          // A-layout u32, 2048
#define OFF_K 2048       // B-layout k=d,n=j, u32 2048
#define OFF_V 4096       // B-layout k=j,n=d, u32 2048
#define OFF_P 6144       // A-layout u32 2048
#define OFF_R 8192       // B-layout k=d,n=band, nnt=16, u32 4096
#define OFF_S1 12288     // f32 [64][68]
#define OFF_S2 16640     // f32 [64][132]
#define OFF_M 25088
#define OFF_L 25152
#define OFF_A 25216
#define ATTN_SMEM_BYTES ((25216 + 64) * 4)

__global__ void __launch_bounds__(256) attn_kernel(const float* __restrict__ rel) {
    extern __shared__ float sm[];
    unsigned* Qs = (unsigned*)sm + OFF_Q;
    unsigned* Ks = (unsigned*)sm + OFF_K;
    unsigned* Vs = (unsigned*)sm + OFF_V;
    unsigned* Ps = (unsigned*)sm + OFF_P;
    unsigned* Rs = (unsigned*)sm + OFF_R;
    float* S1s = sm + OFF_S1;
    float* S2s = sm + OFF_S2;
    float* row_m = sm + OFF_M;
    float* row_l = sm + OFF_L;
    float* row_a = sm + OFF_A;

    const int it = blockIdx.x, bh = blockIdx.y;
    const int b = bh >> 3, h = bh & 7;
    const int i0 = it << 6;
    const int tid = threadIdx.x;
    const int lane = tid & 31, warp = tid >> 5;
    const int g = lane >> 2, tig = lane & 3;

    const float* qb = g_q + (size_t)bh * NL * NDK;
    const float* kb = g_k + (size_t)bh * NL * NDK;
    const float* vb = g_v + (size_t)bh * NL * NDK;

    // load Q tile into A-layout (zero OOB rows)
#pragma unroll
    for (int i = 0; i < 4; i++) {
        int f = tid + (i << 8);
        int r = f >> 4, c4 = (f & 15) << 2;
        float4 v = make_float4(0.f, 0.f, 0.f, 0.f);
        if (i0 + r < NL) v = *(const float4*)&qb[(size_t)(i0 + r) * NDK + c4];
        Qs[a_off16(r, c4, 4)] = bf2(v.x, v.y);
        Qs[a_off16(r, c4 + 2, 4)] = bf2(v.z, v.w);
    }
    if (tid < 64) { row_m[tid] = -1e30f; row_l[tid] = 0.f; }
    float4 O[4] = {};
    __syncthreads();

    for (int jt = 0; jt < 16; jt++) {
        const int j0 = jt << 6;
        // K (pre-scaled, B-layout k=d,n=j): pairs over d
#pragma unroll
        for (int i = 0; i < 4; i++) {
            int f = tid + (i << 8);
            int r = f >> 4, c4 = (f & 15) << 2;
            float4 kv = make_float4(0.f, 0.f, 0.f, 0.f);
            if (j0 + r < NL) kv = *(const float4*)&kb[(size_t)(j0 + r) * NDK + c4];
            Ks[b_off16(c4, r, 8)] = bf2(kv.x * 0.125f, kv.y * 0.125f);
            Ks[b_off16(c4 + 2, r, 8)] = bf2(kv.z * 0.125f, kv.w * 0.125f);
        }
        // V (B-layout k=j,n=d): pairs over j -> load two rows per thread
#pragma unroll
        for (int i = 0; i < 2; i++) {
            int f = tid + (i << 8);
            int rp = f >> 4, c4 = (f & 15) << 2;
            int je = j0 + (rp << 1);
            float4 ve = make_float4(0.f, 0.f, 0.f, 0.f);
            float4 vo = make_float4(0.f, 0.f, 0.f, 0.f);
            if (je < NL) ve = *(const float4*)&vb[(size_t)je * NDK + c4];
            if (je + 1 < NL) vo = *(const float4*)&vb[(size_t)(je + 1) * NDK + c4];
            Vs[b_off16(rp << 1, c4 + 0, 8)] = bf2(ve.x, vo.x);
            Vs[b_off16(rp << 1, c4 + 1, 8)] = bf2(ve.y, vo.y);
            Vs[b_off16(rp << 1, c4 + 2, 8)] = bf2(ve.z, vo.z);
            Vs[b_off16(rp << 1, c4 + 3, 8)] = bf2(ve.w, vo.w);
        }
        // rel band (128 rows) B-layout k=d,n=band: pairs over d
        const int rbase = j0 - i0 + (NL - 1) - 63;
#pragma unroll
        for (int i = 0; i < 8; i++) {
            int f = tid + (i << 8);
            int r = f >> 4, c4 = (f & 15) << 2;
            int rg = rbase + r;
            float4 v = make_float4(0.f, 0.f, 0.f, 0.f);
            if (rg >= 0 && rg < NR) v = *(const float4*)&rel[(size_t)rg * NDK + c4];
            Rs[b_off16(c4, r, 16)] = bf2(v.x, v.y);
            Rs[b_off16(c4 + 2, r, 16)] = bf2(v.z, v.w);
        }
        __syncthreads();

        // S1 = Q @ K^T : warp owns n8-tile `warp`
        {
            float4 s[4] = {};
#pragma unroll
            for (int kt = 0; kt < 4; kt++) {
                uint2 bfr = *(uint2*)&Ks[((kt * 8 + warp) << 6) + (lane << 1)];
#pragma unroll
                for (int mt = 0; mt < 4; mt++) {
                    uint4 afr = *(uint4*)&Qs[((mt * 4 + kt) << 7) + (lane << 2)];
                    mma16(s[mt], afr, bfr);
                }
            }
            int col = (warp << 3) + (tig << 1);
#pragma unroll
            for (int mt = 0; mt < 4; mt++) {
                int r0 = (mt << 4) + g;
                *(float2*)&S1s[r0 * 68 + col] = make_float2(s[mt].x, s[mt].y);
                *(float2*)&S1s[(r0 + 8) * 68 + col] = make_float2(s[mt].z, s[mt].w);
            }
        }
        // S2 = Q @ RelBand^T : warp owns n8-tiles {2w, 2w+1}
        {
            float4 s[4][2] = {};
#pragma unroll
            for (int kt = 0; kt < 4; kt++) {
                uint2 b0 = *(uint2*)&Rs[((kt * 16 + (warp << 1) + 0) << 6) + (lane << 1)];
                uint2 b1 = *(uint2*)&Rs[((kt * 16 + (warp << 1) + 1) << 6) + (lane << 1)];
#pragma unroll
                for (int mt = 0; mt < 4; mt++) {
                    uint4 afr = *(uint4*)&Qs[((mt * 4 + kt) << 7) + (lane << 2)];
                    mma16(s[mt][0], afr, b0);
                    mma16(s[mt][1], afr, b1);
                }
            }
#pragma unroll
            for (int mt = 0; mt < 4; mt++)
#pragma unroll
                for (int nl = 0; nl < 2; nl++) {
                    int col = (((warp << 1) + nl) << 3) + (tig << 1);
                    int r0 = (mt << 4) + g;
                    *(float2*)&S2s[r0 * 132 + col] = make_float2(s[mt][nl].x, s[mt][nl].y);
                    *(float2*)&S2s[(r0 + 8) * 132 + col] = make_float2(s[mt][nl].z, s[mt][nl].w);
                }
        }
        __syncthreads();

        // online softmax with rel gather: S[i][c] = S1[i][c] + S2[i][c-i+63]
        {
            int i = tid >> 2, q = tid & 3;
            int cbase = q << 4;
            float e[16];
            float mx = -1e30f;
#pragma unroll
            for (int c = 0; c < 16; c++) {
                int cc = cbase + c;
                float s = S1s[i * 68 + cc] + S2s[i * 132 + cc - i + 63];
                e[c] = (j0 + cc >= NL) ? -1e30f : s;
                mx = fmaxf(mx, e[c]);
            }
            mx = fmaxf(mx, __shfl_xor_sync(0xffffffffu, mx, 1));
            mx = fmaxf(mx, __shfl_xor_sync(0xffffffffu, mx, 2));
            float mold = row_m[i];
            float mnew = fmaxf(mold, mx);
            float alpha = __expf(mold - mnew);
            float ssum = 0.f;
#pragma unroll
            for (int c = 0; c < 16; c++) {
                float ev = __expf(e[c] - mnew);
                e[c] = ev;
                ssum += ev;
            }
#pragma unroll
            for (int p = 0; p < 8; p++)
                Ps[a_off16(i, cbase + (p << 1), 4)] = bf2(e[p << 1], e[(p << 1) + 1]);
            ssum += __shfl_xor_sync(0xffffffffu, ssum, 1);
            ssum += __shfl_xor_sync(0xffffffffu, ssum, 2);
            if (q == 0) {
                row_m[i] = mnew;
                row_a[i] = alpha;
                row_l[i] = row_l[i] * alpha + ssum;
            }
        }
        __syncthreads();

        // rescale O then O += P @ V (warp owns n8-tile `warp` of dk)
        {
#pragma unroll
            for (int mt = 0; mt < 4; mt++) {
                float a0 = row_a[(mt << 4) + g];
                float a1 = row_a[(mt << 4) + 8 + g];
                O[mt].x *= a0; O[mt].y *= a0;
                O[mt].z *= a1; O[mt].w *= a1;
            }
#pragma unroll
            for (int kt = 0; kt < 4; kt++) {
                uint2 bfr = *(uint2*)&Vs[((kt * 8 + warp) << 6) + (lane << 1)];
#pragma unroll
                for (int mt = 0; mt < 4; mt++) {
                    uint4 afr = *(uint4*)&Ps[((mt * 4 + kt) << 7) + (lane << 2)];
                    mma16(O[mt], afr, bfr);
                }
            }
        }
        __syncthreads();
    }

    // normalize + write ctx into (B, L, D)
#pragma unroll
    for (int mt = 0; mt < 4; mt++) {
        int r0 = (mt << 4) + g, r1 = r0 + 8;
        int col = (warp << 3) + (tig << 1);
        if (i0 + r0 < NL) {
            float inv = 1.f / row_l[r0];
            *(float2*)&g_ctx[((size_t)(b * NL + i0 + r0)) * ND + (h << 6) + col] =
                make_float2(O[mt].x * inv, O[mt].y * inv);
        }
        if (i0 + r1 < NL) {
            float inv = 1.f / row_l[r1];
            *(float2*)&g_ctx[((size_t)(b * NL + i0 + r1)) * ND + (h << 6) + col] =
                make_float2(O[mt].z * inv, O[mt].w * inv);
        }
    }
}

// ---------------- launch ------------------------------------------------------
extern "C" void kernel_launch(void* const* d_in, const int* in_sizes, int n_in,
                              void* d_out, int out_size) {
    const float* x     = (const float*)d_in[0];
    const float* Wq    = (const float*)d_in[1];
    const float* bq    = (const float*)d_in[2];
    const float* Wk    = (const float*)d_in[3];
    const float* bk    = (const float*)d_in[4];
    const float* Wv    = (const float*)d_in[5];
    const float* bv    = (const float*)d_in[6];
    const float* Wo    = (const float*)d_in[7];
    const float* bo    = (const float*)d_in[8];
    const float* rel   = (const float*)d_in[9];
    const float* gamma = (const float*)d_in[10];
    const float* beta  = (const float*)d_in[11];
    float* out = (float*)d_out;

    void *pxn = nullptr, *pq = nullptr, *pk = nullptr, *pv = nullptr, *pctx = nullptr;
    cudaGetSymbolAddress(&pxn, g_xn);
    cudaGetSymbolAddress(&pq, g_q);
    cudaGetSymbolAddress(&pk, g_k);
    cudaGetSymbolAddress(&pv, g_v);
    cudaGetSymbolAddress(&pctx, g_ctx);

    cudaFuncSetAttribute(attn_kernel, cudaFuncAttributeMaxDynamicSharedMemorySize,
                         ATTN_SMEM_BYTES);

    ln_kernel<<<NB * NL, 128>>>(x, gamma, beta);

    dim3 gg(ND / 128, (NB * NL) / 64);  // (4, 125)
    gemm_kernel<<<gg, 256>>>((const float*)pxn, Wq, bq, nullptr, (float*)pq, 0);
    gemm_kernel<<<gg, 256>>>((const float*)pxn, Wk, bk, nullptr, (float*)pk, 0);
    gemm_kernel<<<gg, 256>>>((const float*)pxn, Wv, bv, nullptr, (float*)pv, 0);

    attn_kernel<<<dim3(16, NB * NH), 256, ATTN_SMEM_BYTES>>>(rel);

    gemm_kernel<<<gg, 256>>>((const float*)pctx, Wo, bo, x, out, 1);
}